// round 5
// baseline (speedup 1.0000x reference)
#include <cuda_runtime.h>
#include <cuda_bf16.h>

#define BATCH 32
#define NN    512
#define MM    512
#define DD    64
#define LDIAG 1023           // N + M - 1 anti-diagonals
#define BIGF  1e30f

// Scratch: dot products in diagonal layout  g_Ddiag[b][i+j][i] = dot(X[b][i], Y[b][j])
// 32 * 1023 * 512 * 4B = ~64 MB. Invalid slots are never read by the DP.
__device__ float g_Ddiag[(size_t)BATCH * LDIAG * NN];
// Row squared norms: [0,16384) = ||X[b][i]||^2 at b*512+i ; [16384,32768) = ||Y[b][j]||^2
__device__ float g_norm2[BATCH * (NN + MM)];

// ---------------------------------------------------------------------------
// Kernel 0: row squared norms. One warp per row, float2 coalesced loads.
// ---------------------------------------------------------------------------
__global__ __launch_bounds__(256) void norms_kernel(const float* __restrict__ X,
                                                    const float* __restrict__ Y) {
    int warp = blockIdx.x * 8 + (threadIdx.x >> 5);   // 0 .. 32767
    int lane = threadIdx.x & 31;
    const float* src;
    int r;
    if (warp < BATCH * NN) { src = X; r = warp; }
    else                   { src = Y; r = warp - BATCH * NN; }
    const float2* p = (const float2*)(src + (size_t)r * DD);
    float2 v = p[lane];                                // 32 lanes * float2 = 64 floats
    float acc = v.x * v.x + v.y * v.y;
    #pragma unroll
    for (int o = 16; o > 0; o >>= 1)
        acc += __shfl_xor_sync(0xffffffffu, acc, o);
    if (lane == 0) g_norm2[warp] = acc;
}

// ---------------------------------------------------------------------------
// Kernel 1: dot(X_i, Y_j) for a 64x64 tile, written to diagonal layout.
// 256 threads, 4x4 register micro-tile per thread, smem staged transpose for
// contiguous anti-diagonal stores.
// ---------------------------------------------------------------------------
__global__ __launch_bounds__(256) void dist_kernel(const float* __restrict__ X,
                                                   const float* __restrict__ Y) {
    __shared__ float smemArr[2 * 64 * 65];   // Xs | Ys ; reused as Dt[64][66]
    float* Xs = smemArr;
    float* Ys = smemArr + 64 * 65;

    const int b  = blockIdx.z;
    const int i0 = blockIdx.y * 64;
    const int j0 = blockIdx.x * 64;
    const int tid = threadIdx.x;

    const float* Xb = X + ((size_t)b * NN + i0) * DD;
    const float* Yb = Y + ((size_t)b * MM + j0) * DD;

    // Load tiles (coalesced global, conflict-free smem with pad 65)
    for (int l = tid; l < 64 * 64; l += 256) {
        int r = l >> 6, k = l & 63;
        Xs[r * 65 + k] = Xb[(size_t)r * DD + k];
        Ys[r * 65 + k] = Yb[(size_t)r * DD + k];
    }
    __syncthreads();

    const int tx = tid & 15, ty = tid >> 4;
    float acc[4][4];
    #pragma unroll
    for (int i = 0; i < 4; i++)
        #pragma unroll
        for (int j = 0; j < 4; j++) acc[i][j] = 0.0f;

    const float* xr = Xs + (ty * 4) * 65;
    const float* yr = Ys + (tx * 4) * 65;
    #pragma unroll 8
    for (int k = 0; k < 64; ++k) {
        float a0 = xr[k], a1 = xr[65 + k], a2 = xr[130 + k], a3 = xr[195 + k];
        float b0 = yr[k], b1 = yr[65 + k], b2 = yr[130 + k], b3 = yr[195 + k];
        acc[0][0] += a0 * b0; acc[0][1] += a0 * b1; acc[0][2] += a0 * b2; acc[0][3] += a0 * b3;
        acc[1][0] += a1 * b0; acc[1][1] += a1 * b1; acc[1][2] += a1 * b2; acc[1][3] += a1 * b3;
        acc[2][0] += a2 * b0; acc[2][1] += a2 * b1; acc[2][2] += a2 * b2; acc[2][3] += a2 * b3;
        acc[3][0] += a3 * b0; acc[3][1] += a3 * b1; acc[3][2] += a3 * b2; acc[3][3] += a3 * b3;
    }
    __syncthreads();   // done reading Xs/Ys; reuse smem as Dt

    float* Dt = smemArr;   // [64][66]; diag read addr = 65*il + t -> stride 65 (mod 32 = 1), conflict-free
    #pragma unroll
    for (int i = 0; i < 4; i++)
        #pragma unroll
        for (int j = 0; j < 4; j++)
            Dt[(ty * 4 + i) * 66 + (tx * 4 + j)] = acc[i][j];
    __syncthreads();

    // Write 127 tile anti-diagonals as contiguous runs. 4 groups of 64 threads.
    float* out = g_Ddiag + (size_t)b * LDIAG * NN;
    const int g  = tid >> 6;     // 0..3
    const int lt = tid & 63;
    for (int t = g; t < 127; t += 4) {
        int lo = t - 63; if (lo < 0) lo = 0;
        int hi = t < 63 ? t : 63;
        if (lt <= hi - lo) {
            int il = lo + lt;
            out[(size_t)(i0 + j0 + t) * NN + (i0 + il)] = Dt[il * 66 + (t - il)];
        }
    }
}

// ---------------------------------------------------------------------------
// Kernel 2: soft-DTW DP. One CTA per batch, 512 threads, thread t owns row t.
// Three rotating diagonals in smem, single __syncthreads per step, D prefetched
// one diagonal ahead. Exact log-space softmin with min-trick.
// ---------------------------------------------------------------------------
__global__ __launch_bounds__(512) void dp_kernel(float* __restrict__ outp) {
    __shared__ float R[3][NN + 1];
    __shared__ float y2s[MM];

    const int t = threadIdx.x;
    const int b = blockIdx.x;

    const float x2 = g_norm2[b * NN + t];
    y2s[t] = g_norm2[BATCH * NN + b * MM + t];

    R[0][t] = BIGF; R[1][t] = BIGF; R[2][t] = BIGF;
    if (t == 0) {
        R[0][NN] = BIGF; R[1][NN] = BIGF; R[2][NN] = BIGF;
        R[0][0] = 0.0f;                       // R[0,0] = 0, seen as prev2 at s=2
    }
    __syncthreads();

    const float* Dp = g_Ddiag + (size_t)b * LDIAG * NN + t;
    float dnext = Dp[0];                      // diagonal s=2 (row 0)

    int p2 = 0, p1 = 1, cu = 2;
    float val = 0.0f;

    #pragma unroll 3
    for (int s = 2; s <= NN + MM; ++s) {
        float dot = dnext;
        if (s < NN + MM) dnext = Dp[(size_t)(s - 1) * NN];   // prefetch next diagonal

        int j = s - 2 - t;                    // 0-based column for this cell
        val = BIGF;
        if ((unsigned)j < (unsigned)MM) {
            float a  = R[p2][t];              // R[i-1, j-1]
            float bb = R[p1][t];              // R[i-1, j]
            float c  = R[p1][t + 1];          // R[i,   j-1]
            float m  = fminf(a, fminf(bb, c));
            float sum = __expf(m - a) + __expf(m - bb) + __expf(m - c);
            float Dv  = fmaf(-2.0f, dot, x2 + y2s[j]);
            val = Dv + m - __logf(sum);
        }
        R[cu][t + 1] = val;                   // cu buffer not read this step -> safe pre-barrier
        if (t == 0) R[cu][0] = BIGF;          // boundary R[0, *] = inf
        __syncthreads();
        int tmp = p2; p2 = p1; p1 = cu; cu = tmp;
    }

    if (t == NN - 1) outp[b] = val;           // R[N, M]
}

// ---------------------------------------------------------------------------
extern "C" void kernel_launch(void* const* d_in, const int* in_sizes, int n_in,
                              void* d_out, int out_size) {
    const float* X = (const float*)d_in[0];   // [32, 512, 64]
    const float* Y = (const float*)d_in[1];   // [32, 512, 64]
    float* out = (float*)d_out;               // [32]

    norms_kernel<<<(BATCH * (NN + MM)) / 8, 256>>>(X, Y);
    dist_kernel<<<dim3(MM / 64, NN / 64, BATCH), 256>>>(X, Y);
    dp_kernel<<<BATCH, 512>>>(out);
}